// round 1
// baseline (speedup 1.0000x reference)
#include <cuda_runtime.h>

// Problem constants
#define N_ROWS   1344            // B*C = 64*21
#define R_WIN    32              // windows per row (L/MAX_PL = 1024/32)
#define NWIN     (N_ROWS * R_WIN)  // 43008
#define DM       512             // D_MODEL
#define TGT      4               // MAX_PL/MIN_PL
#define PE_LEN   128             // R_WIN * TGT
#define MAIN_OUT ((long long)N_ROWS * PE_LEN * DM)  // 88080384

// Scratch (no allocation allowed in kernel_launch)
__device__ unsigned char g_pred[NWIN];
__device__ float g_pe[PE_LEN * DM];

// ---------------------------------------------------------------------------
// Kernel A: sinusoidal PE table (128 x 512). 65536 threads, runs in ~2us.
// ---------------------------------------------------------------------------
__global__ void pe_kernel() {
    int idx = blockIdx.x * blockDim.x + threadIdx.x;
    if (idx >= PE_LEN * DM) return;
    int t = idx / DM;
    int d = idx % DM;
    int i2 = (d / 2) * 2;  // even index used for the frequency
    float div = expf(-(float)i2 * (logf(10000.0f) / (float)DM));
    float arg = (float)t * div;
    g_pe[idx] = (d & 1) ? cosf(arg) : sinf(arg);
}

// ---------------------------------------------------------------------------
// Kernel B: classifier. One thread per window.
//   h = relu(x_w @ w1^T + b1)  (64)
//   logits = h @ w2^T + b2     (3)
//   pred = argmax (first-max semantics, matching jnp.argmax)
// Weight loads are warp-converged (all lanes read same address) -> broadcast.
// ---------------------------------------------------------------------------
__global__ void cls_kernel(const float* __restrict__ x,
                           const float* __restrict__ w1,
                           const float* __restrict__ b1,
                           const float* __restrict__ w2,
                           const float* __restrict__ b2) {
    int w = blockIdx.x * blockDim.x + threadIdx.x;
    if (w >= NWIN) return;

    // Load the 32-sample window into registers (contiguous, 128B aligned).
    const float4* xw = (const float4*)(x + (size_t)w * 32);
    float4 xv[8];
#pragma unroll
    for (int i = 0; i < 8; i++) xv[i] = xw[i];

    float l0 = b2[0], l1 = b2[1], l2 = b2[2];

#pragma unroll 4
    for (int h = 0; h < 64; h++) {
        const float4* wr = (const float4*)(w1 + h * 32);
        float a0 = 0.f, a1 = 0.f, a2 = 0.f, a3 = 0.f;
#pragma unroll
        for (int i = 0; i < 8; i++) {
            float4 wv = wr[i];
            a0 = fmaf(wv.x, xv[i].x, a0);
            a1 = fmaf(wv.y, xv[i].y, a1);
            a2 = fmaf(wv.z, xv[i].z, a2);
            a3 = fmaf(wv.w, xv[i].w, a3);
        }
        float hv = b1[h] + ((a0 + a1) + (a2 + a3));
        hv = fmaxf(hv, 0.0f);
        l0 = fmaf(w2[h], hv, l0);
        l1 = fmaf(w2[64 + h], hv, l1);
        l2 = fmaf(w2[128 + h], hv, l2);
    }

    int p = 0;
    float m = l0;
    if (l1 > m) { m = l1; p = 1; }   // strict > keeps first max (argmax semantics)
    if (l2 > m) { m = l2; p = 2; }
    g_pred[w] = (unsigned char)p;
}

// ---------------------------------------------------------------------------
// Kernel C: embedding + repeat + PE + store.
// One block per n (row of 32 windows), 512 threads: thread t owns output dim d=t.
// All three embedding rows for this d are cached in registers (56 floats),
// amortized over 32 windows. x lives in smem, read as broadcast LDS.128.
// pred branch is uniform per window -> no divergence.
// ---------------------------------------------------------------------------
__global__ void __launch_bounds__(512)
emb_kernel(const float* __restrict__ x,
           const float* __restrict__ we0,   // [512][8]
           const float* __restrict__ we1,   // [512][16]
           const float* __restrict__ we2,   // [512][32]
           float* __restrict__ out) {
    __shared__ __align__(16) float s_x[R_WIN * 32];   // 4 KB
    __shared__ unsigned char s_pred[R_WIN];

    int n = blockIdx.x;
    int d = threadIdx.x;

    // Per-thread register weight cache: rows of all 3 tables for dim d.
    float4 r0[2], r1[4], r2[8];
    {
        const float4* p0 = (const float4*)(we0 + d * 8);
        r0[0] = p0[0]; r0[1] = p0[1];
        const float4* p1 = (const float4*)(we1 + d * 16);
#pragma unroll
        for (int i = 0; i < 4; i++) r1[i] = p1[i];
        const float4* p2 = (const float4*)(we2 + d * 32);
#pragma unroll
        for (int i = 0; i < 8; i++) r2[i] = p2[i];
    }

    // Cooperative loads: x row (1024 floats) + 32 preds.
    {
        const float4* xg = (const float4*)(x + (size_t)n * 1024);
        if (d < 256) ((float4*)s_x)[d] = xg[d];
        if (d < R_WIN) s_pred[d] = g_pred[n * R_WIN + d];
    }
    __syncthreads();

    float* outn = out + (size_t)n * (PE_LEN * DM);

#pragma unroll 1
    for (int w = 0; w < R_WIN; w++) {
        int pred = s_pred[w];

        // Broadcast read of the 32-sample window (conflict-free).
        const float4* xq = (const float4*)(s_x + w * 32);
        float4 xv[8];
#pragma unroll
        for (int i = 0; i < 8; i++) xv[i] = xq[i];

        float v0, v1, v2, v3;
        if (pred == 0) {
            // 4 patches of 8; repeat idx = [0,1,2,3]
            float a0, a1, a2, a3;
            a0 = fmaf(r0[0].x, xv[0].x, fmaf(r0[0].y, xv[0].y,
                 fmaf(r0[0].z, xv[0].z, r0[0].w * xv[0].w)));
            a0 += fmaf(r0[1].x, xv[1].x, fmaf(r0[1].y, xv[1].y,
                  fmaf(r0[1].z, xv[1].z, r0[1].w * xv[1].w)));
            a1 = fmaf(r0[0].x, xv[2].x, fmaf(r0[0].y, xv[2].y,
                 fmaf(r0[0].z, xv[2].z, r0[0].w * xv[2].w)));
            a1 += fmaf(r0[1].x, xv[3].x, fmaf(r0[1].y, xv[3].y,
                  fmaf(r0[1].z, xv[3].z, r0[1].w * xv[3].w)));
            a2 = fmaf(r0[0].x, xv[4].x, fmaf(r0[0].y, xv[4].y,
                 fmaf(r0[0].z, xv[4].z, r0[0].w * xv[4].w)));
            a2 += fmaf(r0[1].x, xv[5].x, fmaf(r0[1].y, xv[5].y,
                  fmaf(r0[1].z, xv[5].z, r0[1].w * xv[5].w)));
            a3 = fmaf(r0[0].x, xv[6].x, fmaf(r0[0].y, xv[6].y,
                 fmaf(r0[0].z, xv[6].z, r0[0].w * xv[6].w)));
            a3 += fmaf(r0[1].x, xv[7].x, fmaf(r0[1].y, xv[7].y,
                  fmaf(r0[1].z, xv[7].z, r0[1].w * xv[7].w)));
            v0 = a0; v1 = a1; v2 = a2; v3 = a3;
        } else if (pred == 1) {
            // 2 patches of 16; repeat idx = [0,0,0,1]
            float a = 0.f, b = 0.f;
#pragma unroll
            for (int i = 0; i < 4; i++) {
                a = fmaf(r1[i].x, xv[i].x, a);
                a = fmaf(r1[i].y, xv[i].y, a);
                a = fmaf(r1[i].z, xv[i].z, a);
                a = fmaf(r1[i].w, xv[i].w, a);
            }
#pragma unroll
            for (int i = 0; i < 4; i++) {
                b = fmaf(r1[i].x, xv[4 + i].x, b);
                b = fmaf(r1[i].y, xv[4 + i].y, b);
                b = fmaf(r1[i].z, xv[4 + i].z, b);
                b = fmaf(r1[i].w, xv[4 + i].w, b);
            }
            v0 = a; v1 = a; v2 = a; v3 = b;
        } else {
            // 1 patch of 32; repeat idx = [0,0,0,0]
            float c0 = 0.f, c1 = 0.f, c2 = 0.f, c3 = 0.f;
#pragma unroll
            for (int i = 0; i < 8; i += 4) {
                c0 = fmaf(r2[i].x, xv[i].x, c0);
                c0 = fmaf(r2[i].y, xv[i].y, c0);
                c0 = fmaf(r2[i].z, xv[i].z, c0);
                c0 = fmaf(r2[i].w, xv[i].w, c0);
                c1 = fmaf(r2[i+1].x, xv[i+1].x, c1);
                c1 = fmaf(r2[i+1].y, xv[i+1].y, c1);
                c1 = fmaf(r2[i+1].z, xv[i+1].z, c1);
                c1 = fmaf(r2[i+1].w, xv[i+1].w, c1);
                c2 = fmaf(r2[i+2].x, xv[i+2].x, c2);
                c2 = fmaf(r2[i+2].y, xv[i+2].y, c2);
                c2 = fmaf(r2[i+2].z, xv[i+2].z, c2);
                c2 = fmaf(r2[i+2].w, xv[i+2].w, c2);
                c3 = fmaf(r2[i+3].x, xv[i+3].x, c3);
                c3 = fmaf(r2[i+3].y, xv[i+3].y, c3);
                c3 = fmaf(r2[i+3].z, xv[i+3].z, c3);
                c3 = fmaf(r2[i+3].w, xv[i+3].w, c3);
            }
            float c = (c0 + c1) + (c2 + c3);
            v0 = c; v1 = c; v2 = c; v3 = c;
        }

        const float* pe = g_pe + (w * TGT) * DM + d;   // pos = r*4 + k, r == w
        float* o = outn + (size_t)w * (TGT * DM) + d;
        o[0 * DM] = v0 + pe[0 * DM];
        o[1 * DM] = v1 + pe[1 * DM];
        o[2 * DM] = v2 + pe[2 * DM];
        o[3 * DM] = v3 + pe[3 * DM];
    }
}

// ---------------------------------------------------------------------------
// Tail: reference returns (x_patch, C). If the harness appends C, fill it.
// ---------------------------------------------------------------------------
__global__ void tail_kernel(float* __restrict__ out, long long start, long long total) {
    long long i = start + blockIdx.x * (long long)blockDim.x + threadIdx.x;
    if (i < total) out[i] = 21.0f;   // C = 21
}

extern "C" void kernel_launch(void* const* d_in, const int* in_sizes, int n_in,
                              void* d_out, int out_size) {
    const float* x   = (const float*)d_in[0];
    const float* w1  = (const float*)d_in[1];
    const float* b1  = (const float*)d_in[2];
    const float* w2  = (const float*)d_in[3];
    const float* b2  = (const float*)d_in[4];
    const float* we0 = (const float*)d_in[5];
    const float* we1 = (const float*)d_in[6];
    const float* we2 = (const float*)d_in[7];
    float* out = (float*)d_out;

    pe_kernel<<<(PE_LEN * DM + 255) / 256, 256>>>();
    cls_kernel<<<(NWIN + 255) / 256, 256>>>(x, w1, b1, w2, b2);
    emb_kernel<<<N_ROWS, 512>>>(x, we0, we1, we2, out);

    long long total = (long long)out_size;
    if (total > MAIN_OUT) {
        long long tail = total - MAIN_OUT;
        int blocks = (int)((tail + 255) / 256);
        tail_kernel<<<blocks, 256>>>(out, MAIN_OUT, total);
    }
}

// round 2
// speedup vs baseline: 1.0305x; 1.0305x over previous
#include <cuda_runtime.h>

// Problem constants
#define N_ROWS   1344              // B*C = 64*21
#define R_WIN    32                // windows per row (L/MAX_PL = 1024/32)
#define NWIN     (N_ROWS * R_WIN)  // 43008
#define DM       512               // D_MODEL
#define TGT      4                 // MAX_PL/MIN_PL
#define PE_LEN   128               // R_WIN * TGT
#define MAIN_OUT ((long long)N_ROWS * PE_LEN * DM)  // 88080384

// Scratch (no allocation allowed in kernel_launch)
__device__ unsigned char g_pred[NWIN];
__device__ float g_pe[PE_LEN * DM];

// ---------------------------------------------------------------------------
// Kernel A: sinusoidal PE table (128 x 512).
// ---------------------------------------------------------------------------
__global__ void pe_kernel() {
    int idx = blockIdx.x * blockDim.x + threadIdx.x;
    if (idx >= PE_LEN * DM) return;
    int t = idx / DM;
    int d = idx % DM;
    int i2 = (d / 2) * 2;
    float div = expf(-(float)i2 * (logf(10000.0f) / (float)DM));
    float arg = (float)t * div;
    g_pe[idx] = (d & 1) ? cosf(arg) : sinf(arg);
}

// ---------------------------------------------------------------------------
// Kernel B: classifier. One thread per window. Weight loads are
// warp-converged broadcasts.
// ---------------------------------------------------------------------------
__global__ void __launch_bounds__(256)
cls_kernel(const float* __restrict__ x,
           const float* __restrict__ w1,
           const float* __restrict__ b1,
           const float* __restrict__ w2,
           const float* __restrict__ b2) {
    int w = blockIdx.x * blockDim.x + threadIdx.x;
    if (w >= NWIN) return;

    const float4* xw = (const float4*)(x + (size_t)w * 32);
    float4 xv[8];
#pragma unroll
    for (int i = 0; i < 8; i++) xv[i] = xw[i];

    float l0 = b2[0], l1 = b2[1], l2 = b2[2];

#pragma unroll 4
    for (int h = 0; h < 64; h++) {
        const float4* wr = (const float4*)(w1 + h * 32);
        float a0 = 0.f, a1 = 0.f, a2 = 0.f, a3 = 0.f;
#pragma unroll
        for (int i = 0; i < 8; i++) {
            float4 wv = wr[i];
            a0 = fmaf(wv.x, xv[i].x, a0);
            a1 = fmaf(wv.y, xv[i].y, a1);
            a2 = fmaf(wv.z, xv[i].z, a2);
            a3 = fmaf(wv.w, xv[i].w, a3);
        }
        float hv = b1[h] + ((a0 + a1) + (a2 + a3));
        hv = fmaxf(hv, 0.0f);
        l0 = fmaf(w2[h], hv, l0);
        l1 = fmaf(w2[64 + h], hv, l1);
        l2 = fmaf(w2[128 + h], hv, l2);
    }

    int p = 0;
    float m = l0;
    if (l1 > m) { m = l1; p = 1; }
    if (l2 > m) { m = l2; p = 2; }
    g_pred[w] = (unsigned char)p;
}

// ---------------------------------------------------------------------------
// Kernel C: embedding + repeat + PE + store.
// 256 threads/block, TWO blocks per n (blockIdx covers half the dims each):
//   d = (blockIdx.x & 1) * 256 + threadIdx.x
// 256 threads => up to 255 regs/thread, so the 56-float weight cache +
// 32-float window live set fits WITHOUT spills (the R1 killer), and at
// ~112 regs we keep 2 CTAs/SM resident.
// ---------------------------------------------------------------------------
__global__ void __launch_bounds__(256)
emb_kernel(const float* __restrict__ x,
           const float* __restrict__ we0,   // [512][8]
           const float* __restrict__ we1,   // [512][16]
           const float* __restrict__ we2,   // [512][32]
           float* __restrict__ out) {
    __shared__ __align__(16) float s_x[R_WIN * 32];   // 4 KB
    __shared__ unsigned char s_pred[R_WIN];

    int n    = blockIdx.x >> 1;
    int dblk = (blockIdx.x & 1) * 256;
    int d    = dblk + threadIdx.x;

    // Per-thread register weight cache: rows of all 3 tables for dim d.
    float4 r0[2], r1[4], r2[8];
    {
        const float4* p0 = (const float4*)(we0 + d * 8);
        r0[0] = p0[0]; r0[1] = p0[1];
        const float4* p1 = (const float4*)(we1 + d * 16);
#pragma unroll
        for (int i = 0; i < 4; i++) r1[i] = p1[i];
        const float4* p2 = (const float4*)(we2 + d * 32);
#pragma unroll
        for (int i = 0; i < 8; i++) r2[i] = p2[i];
    }

    // Cooperative loads: x row (1024 floats = 256 float4) + 32 preds.
    {
        const float4* xg = (const float4*)(x + (size_t)n * 1024);
        ((float4*)s_x)[threadIdx.x] = xg[threadIdx.x];
        if (threadIdx.x < R_WIN) s_pred[threadIdx.x] = g_pred[n * R_WIN + threadIdx.x];
    }
    __syncthreads();

    float* outn = out + (size_t)n * (PE_LEN * DM);

#pragma unroll 1
    for (int w = 0; w < R_WIN; w++) {
        int pred = s_pred[w];

        const float4* xq = (const float4*)(s_x + w * 32);
        float4 xv[8];
#pragma unroll
        for (int i = 0; i < 8; i++) xv[i] = xq[i];

        float v0, v1, v2, v3;
        if (pred == 0) {
            // 4 patches of 8; repeat idx = [0,1,2,3]
            float a0, a1, a2, a3;
            a0 = fmaf(r0[0].x, xv[0].x, fmaf(r0[0].y, xv[0].y,
                 fmaf(r0[0].z, xv[0].z, r0[0].w * xv[0].w)));
            a0 += fmaf(r0[1].x, xv[1].x, fmaf(r0[1].y, xv[1].y,
                  fmaf(r0[1].z, xv[1].z, r0[1].w * xv[1].w)));
            a1 = fmaf(r0[0].x, xv[2].x, fmaf(r0[0].y, xv[2].y,
                 fmaf(r0[0].z, xv[2].z, r0[0].w * xv[2].w)));
            a1 += fmaf(r0[1].x, xv[3].x, fmaf(r0[1].y, xv[3].y,
                  fmaf(r0[1].z, xv[3].z, r0[1].w * xv[3].w)));
            a2 = fmaf(r0[0].x, xv[4].x, fmaf(r0[0].y, xv[4].y,
                 fmaf(r0[0].z, xv[4].z, r0[0].w * xv[4].w)));
            a2 += fmaf(r0[1].x, xv[5].x, fmaf(r0[1].y, xv[5].y,
                  fmaf(r0[1].z, xv[5].z, r0[1].w * xv[5].w)));
            a3 = fmaf(r0[0].x, xv[6].x, fmaf(r0[0].y, xv[6].y,
                 fmaf(r0[0].z, xv[6].z, r0[0].w * xv[6].w)));
            a3 += fmaf(r0[1].x, xv[7].x, fmaf(r0[1].y, xv[7].y,
                  fmaf(r0[1].z, xv[7].z, r0[1].w * xv[7].w)));
            v0 = a0; v1 = a1; v2 = a2; v3 = a3;
        } else if (pred == 1) {
            // 2 patches of 16; repeat idx = [0,0,0,1]
            float a = 0.f, b = 0.f;
#pragma unroll
            for (int i = 0; i < 4; i++) {
                a = fmaf(r1[i].x, xv[i].x, a);
                a = fmaf(r1[i].y, xv[i].y, a);
                a = fmaf(r1[i].z, xv[i].z, a);
                a = fmaf(r1[i].w, xv[i].w, a);
            }
#pragma unroll
            for (int i = 0; i < 4; i++) {
                b = fmaf(r1[i].x, xv[4 + i].x, b);
                b = fmaf(r1[i].y, xv[4 + i].y, b);
                b = fmaf(r1[i].z, xv[4 + i].z, b);
                b = fmaf(r1[i].w, xv[4 + i].w, b);
            }
            v0 = a; v1 = a; v2 = a; v3 = b;
        } else {
            // 1 patch of 32; repeat idx = [0,0,0,0]
            float c0 = 0.f, c1 = 0.f, c2 = 0.f, c3 = 0.f;
#pragma unroll
            for (int i = 0; i < 8; i += 4) {
                c0 = fmaf(r2[i].x,   xv[i].x,   c0);
                c0 = fmaf(r2[i].y,   xv[i].y,   c0);
                c0 = fmaf(r2[i].z,   xv[i].z,   c0);
                c0 = fmaf(r2[i].w,   xv[i].w,   c0);
                c1 = fmaf(r2[i+1].x, xv[i+1].x, c1);
                c1 = fmaf(r2[i+1].y, xv[i+1].y, c1);
                c1 = fmaf(r2[i+1].z, xv[i+1].z, c1);
                c1 = fmaf(r2[i+1].w, xv[i+1].w, c1);
                c2 = fmaf(r2[i+2].x, xv[i+2].x, c2);
                c2 = fmaf(r2[i+2].y, xv[i+2].y, c2);
                c2 = fmaf(r2[i+2].z, xv[i+2].z, c2);
                c2 = fmaf(r2[i+2].w, xv[i+2].w, c2);
                c3 = fmaf(r2[i+3].x, xv[i+3].x, c3);
                c3 = fmaf(r2[i+3].y, xv[i+3].y, c3);
                c3 = fmaf(r2[i+3].z, xv[i+3].z, c3);
                c3 = fmaf(r2[i+3].w, xv[i+3].w, c3);
            }
            float c = (c0 + c1) + (c2 + c3);
            v0 = c; v1 = c; v2 = c; v3 = c;
        }

        const float* pe = g_pe + (w * TGT) * DM + d;
        float* o = outn + (size_t)w * (TGT * DM) + d;
        o[0 * DM] = v0 + pe[0 * DM];
        o[1 * DM] = v1 + pe[1 * DM];
        o[2 * DM] = v2 + pe[2 * DM];
        o[3 * DM] = v3 + pe[3 * DM];
    }
}

// ---------------------------------------------------------------------------
// Tail: reference returns (x_patch, C); fill any appended scalar region.
// ---------------------------------------------------------------------------
__global__ void tail_kernel(float* __restrict__ out, long long start, long long total) {
    long long i = start + blockIdx.x * (long long)blockDim.x + threadIdx.x;
    if (i < total) out[i] = 21.0f;   // C = 21
}

extern "C" void kernel_launch(void* const* d_in, const int* in_sizes, int n_in,
                              void* d_out, int out_size) {
    const float* x   = (const float*)d_in[0];
    const float* w1  = (const float*)d_in[1];
    const float* b1  = (const float*)d_in[2];
    const float* w2  = (const float*)d_in[3];
    const float* b2  = (const float*)d_in[4];
    const float* we0 = (const float*)d_in[5];
    const float* we1 = (const float*)d_in[6];
    const float* we2 = (const float*)d_in[7];
    float* out = (float*)d_out;

    pe_kernel<<<(PE_LEN * DM + 255) / 256, 256>>>();
    cls_kernel<<<(NWIN + 255) / 256, 256>>>(x, w1, b1, w2, b2);
    emb_kernel<<<N_ROWS * 2, 256>>>(x, we0, we1, we2, out);

    long long total = (long long)out_size;
    if (total > MAIN_OUT) {
        long long tail = total - MAIN_OUT;
        int blocks = (int)((tail + 255) / 256);
        tail_kernel<<<blocks, 256>>>(out, MAIN_OUT, total);
    }
}

// round 3
// speedup vs baseline: 2.1916x; 2.1267x over previous
#include <cuda_runtime.h>

// Problem constants
#define N_ROWS   1344              // B*C = 64*21
#define R_WIN    32                // windows per row (L/MAX_PL = 1024/32)
#define NWIN     (N_ROWS * R_WIN)  // 43008
#define DM       512               // D_MODEL
#define TGT      4                 // MAX_PL/MIN_PL
#define PE_LEN   128               // R_WIN * TGT
#define MAIN_OUT ((long long)N_ROWS * PE_LEN * DM)  // 88080384
#define CLS_BLOCKS ((NWIN + 255) / 256)             // 168

// Scratch (no allocation allowed in kernel_launch)
__device__ unsigned char g_pred[NWIN];

// ---------------------------------------------------------------------------
// Kernel 1: classifier (+ tail fill for any appended output region).
// One thread per window; weight loads are warp-converged broadcasts.
// ---------------------------------------------------------------------------
__global__ void __launch_bounds__(256)
pre_kernel(const float* __restrict__ x,
           const float* __restrict__ w1,
           const float* __restrict__ b1,
           const float* __restrict__ w2,
           const float* __restrict__ b2,
           float* __restrict__ out,
           long long tail_start, long long total) {
    int bid = blockIdx.x;
    if (bid >= CLS_BLOCKS) {
        // Tail region: reference returns (x_patch, C=21).
        long long i = tail_start + (long long)(bid - CLS_BLOCKS) * 256 + threadIdx.x;
        if (i < total) out[i] = 21.0f;
        return;
    }

    int w = bid * blockDim.x + threadIdx.x;
    if (w >= NWIN) return;

    const float4* xw = (const float4*)(x + (size_t)w * 32);
    float4 xv[8];
#pragma unroll
    for (int i = 0; i < 8; i++) xv[i] = xw[i];

    float l0 = b2[0], l1 = b2[1], l2 = b2[2];

#pragma unroll 4
    for (int h = 0; h < 64; h++) {
        const float4* wr = (const float4*)(w1 + h * 32);
        float a0 = 0.f, a1 = 0.f, a2 = 0.f, a3 = 0.f;
#pragma unroll
        for (int i = 0; i < 8; i++) {
            float4 wv = wr[i];
            a0 = fmaf(wv.x, xv[i].x, a0);
            a1 = fmaf(wv.y, xv[i].y, a1);
            a2 = fmaf(wv.z, xv[i].z, a2);
            a3 = fmaf(wv.w, xv[i].w, a3);
        }
        float hv = b1[h] + ((a0 + a1) + (a2 + a3));
        hv = fmaxf(hv, 0.0f);
        l0 = fmaf(w2[h], hv, l0);
        l1 = fmaf(w2[64 + h], hv, l1);
        l2 = fmaf(w2[128 + h], hv, l2);
    }

    int p = 0;
    float m = l0;
    if (l1 > m) { m = l1; p = 1; }   // strict > keeps first-max (jnp.argmax)
    if (l2 > m) { m = l2; p = 2; }
    g_pred[w] = (unsigned char)p;
}

// ---------------------------------------------------------------------------
// Kernel 2: embedding + repeat + PE + store.
// 256 threads/block, two blocks per n: d = (blockIdx&1)*256 + tid.
// Weight rows for this thread's d live in registers (56 floats).
// PE is computed by an in-register rotation recurrence (NO table, NO loads):
//   s_{t+1} = s_t*cos(D) + c_t*sin(D),  c_{t+1} = c_t*cos(D) - s_t*sin(D)
// with D = exp(-(d&~1) * ln(10000)/512); pe(t,d) = (d odd) ? c_t : s_t.
// ---------------------------------------------------------------------------
__global__ void __launch_bounds__(256)
emb_kernel(const float* __restrict__ x,
           const float* __restrict__ we0,   // [512][8]
           const float* __restrict__ we1,   // [512][16]
           const float* __restrict__ we2,   // [512][32]
           float* __restrict__ out) {
    __shared__ __align__(16) float s_x[R_WIN * 32];   // 4 KB
    __shared__ unsigned char s_pred[R_WIN];

    int n    = blockIdx.x >> 1;
    int dblk = (blockIdx.x & 1) * 256;
    int d    = dblk + threadIdx.x;

    // PE recurrence setup (once per thread).
    const float kLn = -9.21034037197618f / (float)DM;   // -ln(10000)/512
    float delta = expf((float)(d & ~1) * kLn);
    float sd, cd;
    sincosf(delta, &sd, &cd);
    float s = 0.0f, c = 1.0f;     // sin(0), cos(0)
    bool use_cos = (d & 1);

    // Per-thread register weight cache: rows of all 3 tables for dim d.
    float4 r0[2], r1[4], r2[8];
    {
        const float4* p0 = (const float4*)(we0 + d * 8);
        r0[0] = p0[0]; r0[1] = p0[1];
        const float4* p1 = (const float4*)(we1 + d * 16);
#pragma unroll
        for (int i = 0; i < 4; i++) r1[i] = p1[i];
        const float4* p2 = (const float4*)(we2 + d * 32);
#pragma unroll
        for (int i = 0; i < 8; i++) r2[i] = p2[i];
    }

    // Cooperative loads: x row (1024 floats = 256 float4) + 32 preds.
    {
        const float4* xg = (const float4*)(x + (size_t)n * 1024);
        ((float4*)s_x)[threadIdx.x] = xg[threadIdx.x];
        if (threadIdx.x < R_WIN) s_pred[threadIdx.x] = g_pred[n * R_WIN + threadIdx.x];
    }
    __syncthreads();

    float* outn = out + (size_t)n * (PE_LEN * DM);

#pragma unroll 1
    for (int w = 0; w < R_WIN; w++) {
        int pred = s_pred[w];

        const float4* xq = (const float4*)(s_x + w * 32);
        float4 xv[8];
#pragma unroll
        for (int i = 0; i < 8; i++) xv[i] = xq[i];

        float v0, v1, v2, v3;
        if (pred == 0) {
            // 4 patches of 8; repeat idx = [0,1,2,3]
            float a0, a1, a2, a3;
            a0 = fmaf(r0[0].x, xv[0].x, fmaf(r0[0].y, xv[0].y,
                 fmaf(r0[0].z, xv[0].z, r0[0].w * xv[0].w)));
            a0 += fmaf(r0[1].x, xv[1].x, fmaf(r0[1].y, xv[1].y,
                  fmaf(r0[1].z, xv[1].z, r0[1].w * xv[1].w)));
            a1 = fmaf(r0[0].x, xv[2].x, fmaf(r0[0].y, xv[2].y,
                 fmaf(r0[0].z, xv[2].z, r0[0].w * xv[2].w)));
            a1 += fmaf(r0[1].x, xv[3].x, fmaf(r0[1].y, xv[3].y,
                  fmaf(r0[1].z, xv[3].z, r0[1].w * xv[3].w)));
            a2 = fmaf(r0[0].x, xv[4].x, fmaf(r0[0].y, xv[4].y,
                 fmaf(r0[0].z, xv[4].z, r0[0].w * xv[4].w)));
            a2 += fmaf(r0[1].x, xv[5].x, fmaf(r0[1].y, xv[5].y,
                  fmaf(r0[1].z, xv[5].z, r0[1].w * xv[5].w)));
            a3 = fmaf(r0[0].x, xv[6].x, fmaf(r0[0].y, xv[6].y,
                 fmaf(r0[0].z, xv[6].z, r0[0].w * xv[6].w)));
            a3 += fmaf(r0[1].x, xv[7].x, fmaf(r0[1].y, xv[7].y,
                  fmaf(r0[1].z, xv[7].z, r0[1].w * xv[7].w)));
            v0 = a0; v1 = a1; v2 = a2; v3 = a3;
        } else if (pred == 1) {
            // 2 patches of 16; repeat idx = [0,0,0,1]
            float a = 0.f, b = 0.f;
#pragma unroll
            for (int i = 0; i < 4; i++) {
                a = fmaf(r1[i].x, xv[i].x, a);
                a = fmaf(r1[i].y, xv[i].y, a);
                a = fmaf(r1[i].z, xv[i].z, a);
                a = fmaf(r1[i].w, xv[i].w, a);
            }
#pragma unroll
            for (int i = 0; i < 4; i++) {
                b = fmaf(r1[i].x, xv[4 + i].x, b);
                b = fmaf(r1[i].y, xv[4 + i].y, b);
                b = fmaf(r1[i].z, xv[4 + i].z, b);
                b = fmaf(r1[i].w, xv[4 + i].w, b);
            }
            v0 = a; v1 = a; v2 = a; v3 = b;
        } else {
            // 1 patch of 32; repeat idx = [0,0,0,0]
            float c0 = 0.f, c1 = 0.f, c2 = 0.f, c3 = 0.f;
#pragma unroll
            for (int i = 0; i < 8; i += 4) {
                c0 = fmaf(r2[i].x,   xv[i].x,   c0);
                c0 = fmaf(r2[i].y,   xv[i].y,   c0);
                c0 = fmaf(r2[i].z,   xv[i].z,   c0);
                c0 = fmaf(r2[i].w,   xv[i].w,   c0);
                c1 = fmaf(r2[i+1].x, xv[i+1].x, c1);
                c1 = fmaf(r2[i+1].y, xv[i+1].y, c1);
                c1 = fmaf(r2[i+1].z, xv[i+1].z, c1);
                c1 = fmaf(r2[i+1].w, xv[i+1].w, c1);
                c2 = fmaf(r2[i+2].x, xv[i+2].x, c2);
                c2 = fmaf(r2[i+2].y, xv[i+2].y, c2);
                c2 = fmaf(r2[i+2].z, xv[i+2].z, c2);
                c2 = fmaf(r2[i+2].w, xv[i+2].w, c2);
                c3 = fmaf(r2[i+3].x, xv[i+3].x, c3);
                c3 = fmaf(r2[i+3].y, xv[i+3].y, c3);
                c3 = fmaf(r2[i+3].z, xv[i+3].z, c3);
                c3 = fmaf(r2[i+3].w, xv[i+3].w, c3);
            }
            float cc = (c0 + c1) + (c2 + c3);
            v0 = cc; v1 = cc; v2 = cc; v3 = cc;
        }

        // PE via rotation recurrence — 4 positions per window, zero loads.
        float p0 = use_cos ? c : s;
        { float ns = fmaf(s, cd, c * sd); float nc = fmaf(c, cd, -s * sd); s = ns; c = nc; }
        float p1 = use_cos ? c : s;
        { float ns = fmaf(s, cd, c * sd); float nc = fmaf(c, cd, -s * sd); s = ns; c = nc; }
        float p2 = use_cos ? c : s;
        { float ns = fmaf(s, cd, c * sd); float nc = fmaf(c, cd, -s * sd); s = ns; c = nc; }
        float p3 = use_cos ? c : s;
        { float ns = fmaf(s, cd, c * sd); float nc = fmaf(c, cd, -s * sd); s = ns; c = nc; }

        float* o = outn + (size_t)w * (TGT * DM) + d;
        o[0 * DM] = v0 + p0;
        o[1 * DM] = v1 + p1;
        o[2 * DM] = v2 + p2;
        o[3 * DM] = v3 + p3;
    }
}

extern "C" void kernel_launch(void* const* d_in, const int* in_sizes, int n_in,
                              void* d_out, int out_size) {
    const float* x   = (const float*)d_in[0];
    const float* w1  = (const float*)d_in[1];
    const float* b1  = (const float*)d_in[2];
    const float* w2  = (const float*)d_in[3];
    const float* b2  = (const float*)d_in[4];
    const float* we0 = (const float*)d_in[5];
    const float* we1 = (const float*)d_in[6];
    const float* we2 = (const float*)d_in[7];
    float* out = (float*)d_out;

    long long total = (long long)out_size;
    long long tail  = (total > MAIN_OUT) ? (total - MAIN_OUT) : 0;
    int tail_blocks = (int)((tail + 255) / 256);

    pre_kernel<<<CLS_BLOCKS + tail_blocks, 256>>>(x, w1, b1, w2, b2,
                                                  out, MAIN_OUT, total);
    emb_kernel<<<N_ROWS * 2, 256>>>(x, we0, we1, we2, out);
}